// round 13
// baseline (speedup 1.0000x reference)
#include <cuda_runtime.h>
#include <cuda_bf16.h>
#include <cstdint>

// y[m, i2*32+i1] = sum_{j2,j1} x[m,j2*32+j1] * W2[i2,j2] * W1[i1,j1] + bias
// Stage1: T = X @ W1^T (A-frags straight from gmem, sigma k-permuted;
//         W1^T B-frags in regs). Stage2: G = W2 @ T (W2 A-frags in regs;
//         T via movmatrix). tau makes outputs contiguous -> STG.128.
// R13: TWO independent rows per warp, staggered so row B's DRAM latency is
// covered by row A's compute (true dual-chain, unlike R10's idle prefetch).
// __launch_bounds__(128,3) pins <=170 regs -> 3 CTAs/SM guaranteed.
// mma.sync.m16n8k16 bf16, fp32 accuracy via 3-term hi/lo split.

typedef unsigned int u32;

#define RS 80                 // weight staging row stride (bytes)
#define NW 4                  // warps per CTA

__shared__ __align__(16) char swts[10240];     // W1h@0 W1l@2560 W2h@5120 W2l@7680
__shared__ __align__(16) float4 pbias4[256];   // [t][lane] tau/frag-permuted bias

__device__ __forceinline__ u32 smem_u32(const void* p) {
    u32 a;
    asm("{ .reg .u64 t; cvta.to.shared.u64 t, %1; cvt.u32.u64 %0, t; }"
        : "=r"(a) : "l"(p));
    return a;
}
__device__ __forceinline__ void ldm_x4(u32* r, u32 addr) {
    asm volatile("ldmatrix.sync.aligned.m8n8.x4.shared.b16 {%0,%1,%2,%3}, [%4];"
                 : "=r"(r[0]), "=r"(r[1]), "=r"(r[2]), "=r"(r[3]) : "r"(addr));
}
__device__ __forceinline__ u32 movm(u32 v) {
    u32 d;
    asm("movmatrix.sync.aligned.m8n8.trans.b16 %0, %1;" : "=r"(d) : "r"(v));
    return d;
}
__device__ __forceinline__ void mma_bf16(float* c, const u32* a, const u32* b) {
    asm volatile(
        "mma.sync.aligned.m16n8k16.row.col.f32.bf16.bf16.f32 "
        "{%0,%1,%2,%3}, {%4,%5,%6,%7}, {%8,%9}, {%0,%1,%2,%3};"
        : "+f"(c[0]), "+f"(c[1]), "+f"(c[2]), "+f"(c[3])
        : "r"(a[0]), "r"(a[1]), "r"(a[2]), "r"(a[3]), "r"(b[0]), "r"(b[1]));
}
// h = bf16x2(a -> low half, b -> high half); l = residuals
__device__ __forceinline__ void split2(float a, float b, u32& h, u32& l) {
    asm("cvt.rn.bf16x2.f32 %0, %1, %2;" : "=r"(h) : "f"(b), "f"(a));
    float ha = __uint_as_float(h << 16);
    float hb = __uint_as_float(h & 0xFFFF0000u);
    float ra = a - ha, rb = b - hb;
    asm("cvt.rn.bf16x2.f32 %0, %1, %2;" : "=r"(l) : "f"(rb), "f"(ra));
}
// split 32 floats, store hi/lo 64B rows at rowPtr / rowPtr+2560
__device__ __forceinline__ void split_store_row(char* rowPtr, const float* v) {
    u32 hw[16], lw[16];
#pragma unroll
    for (int p = 0; p < 16; p++) split2(v[2 * p], v[2 * p + 1], hw[p], lw[p]);
#pragma unroll
    for (int c = 0; c < 4; c++) {
        *(uint4*)(rowPtr + c * 16) =
            make_uint4(hw[4 * c], hw[4 * c + 1], hw[4 * c + 2], hw[4 * c + 3]);
        *(uint4*)(rowPtr + 2560 + c * 16) =
            make_uint4(lw[4 * c], lw[4 * c + 1], lw[4 * c + 2], lw[4 * c + 3]);
    }
}
// sigma: frag k-pos (within 16-block) -> physical col (within 16-block)
__device__ __forceinline__ int sigma16(int k) {
    return 4 * ((k & 7) >> 1) + 2 * (k >> 3) + (k & 1);
}
// tau: frag n-pos -> physical i1 col (involution, global 0..31)
__device__ __forceinline__ int tau32(int n) {
    return 8 * ((n & 7) >> 1) + 2 * (n >> 3) + (n & 1);
}

__global__ void __launch_bounds__(NW * 32, 3)
kron_mma9_kernel(const float* __restrict__ x,
                 const float* __restrict__ w1,
                 const float* __restrict__ w2,
                 const float* __restrict__ bias,
                 float* __restrict__ out,
                 int rows)
{
    const int tid  = threadIdx.x;
    const int lane = tid & 31;
    const int wrp  = tid >> 5;

    const int lq = lane >> 2;           // frag row within 8-block
    const int lr = lane & 3;            // quad index r

    const u32 laneOff = ((lane & 7) + 8 * ((lane >> 3) & 1)) * RS +
                        ((lane >> 4) << 4);

    // ---- one-time staging ----
    if (wrp == 0) {
        // M1[nu][c] = W1[tau(nu)][16*(c>>4)+sigma(c&15)]  (lane = nu)
        float v[32];
        const float* wrow = w1 + tau32(lane) * 32;
#pragma unroll
        for (int c = 0; c < 32; c++)
            v[c] = wrow[16 * (c >> 4) + sigma16(c & 15)];
        split_store_row(swts + 0 + lane * RS, v);
    } else if (wrp == 1) {
        // M2[i2][j2] = W2 row-major (identity perms on stage-2 M and K)
        float v[32];
        const float4* r = (const float4*)(w2 + lane * 32);
#pragma unroll
        for (int q = 0; q < 8; q++) {
            float4 t = r[q];
            v[4*q] = t.x; v[4*q+1] = t.y; v[4*q+2] = t.z; v[4*q+3] = t.w;
        }
        split_store_row(swts + 5120 + lane * RS, v);
    }
    // pbias4[t=mt*4+nt][lane]: physical (row 16mt+lq(+8), col 8*lr+2*nt, +1)
    for (int t = wrp; t < 8; t += NW) {
        int mt = t >> 2, nt = t & 3;
        int row = 16 * mt + lq;
        int col = 8 * lr + 2 * nt;
        pbias4[t * 32 + lane] =
            make_float4(bias[row * 32 + col], bias[row * 32 + col + 1],
                        bias[(row + 8) * 32 + col], bias[(row + 8) * 32 + col + 1]);
    }
    __syncthreads();

    // ---- invariant weight fragments in registers ----
    const u32 s0 = smem_u32(swts);
    u32 w1Bh[2][4][2], w1Bl[2][4][2];   // [kt][nt][reg]
#pragma unroll
    for (int a = 0; a < 2; a++)
#pragma unroll
        for (int b = 0; b < 2; b++) {
            u32 r[4];
            ldm_x4(r, s0 + 0 + a * (16 * RS) + b * 32 + laneOff);
            w1Bh[b][2*a][0] = r[0]; w1Bh[b][2*a+1][0] = r[1];
            w1Bh[b][2*a][1] = r[2]; w1Bh[b][2*a+1][1] = r[3];
            ldm_x4(r, s0 + 2560 + a * (16 * RS) + b * 32 + laneOff);
            w1Bl[b][2*a][0] = r[0]; w1Bl[b][2*a+1][0] = r[1];
            w1Bl[b][2*a][1] = r[2]; w1Bl[b][2*a+1][1] = r[3];
        }
    u32 w2Ah[2][2][4], w2Al[2][2][4];   // [mt][kt][4]
#pragma unroll
    for (int mt = 0; mt < 2; mt++)
#pragma unroll
        for (int kt = 0; kt < 2; kt++) {
            ldm_x4(w2Ah[mt][kt], s0 + 5120 + mt * (16 * RS) + kt * 32 + laneOff);
            ldm_x4(w2Al[mt][kt], s0 + 7680 + mt * (16 * RS) + kt * 32 + laneOff);
        }
    __syncthreads();

    const int gp    = blockIdx.x * NW + wrp;   // warp's pair index
    const int np    = gridDim.x * NW;          // pairs stride
    const int pairs = rows >> 1;

    for (int p = gp; p < pairs; p += np) {
        const float* xbA = x + (size_t)(2 * p) * 1024;
        const float* xbB = xbA + 1024;

        // ---- load BOTH rows' X up front (16 LDG.128 in flight) ----
        float4 xvA[2][2][2], xvB[2][2][2];   // [mt][kt][h]
#pragma unroll
        for (int mt = 0; mt < 2; mt++)
#pragma unroll
            for (int kt = 0; kt < 2; kt++) {
                int base = (16 * mt + lq) * 32 + 16 * kt + 4 * lr;
                xvA[mt][kt][0] = *(const float4*)(xbA + base);
                xvA[mt][kt][1] = *(const float4*)(xbA + base + 256);
                xvB[mt][kt][0] = *(const float4*)(xbB + base);
                xvB[mt][kt][1] = *(const float4*)(xbB + base + 256);
            }

        u32 XAh[2][2][4], XAl[2][2][4];   // reused for A then B
        float acc[32];                    // reused for A then B
        u32 TAh[2][4][2], TAl[2][4][2];   // row A's stage-2 B-frags
        u32 TBh[2][4][2], TBl[2][4][2];   // row B's stage-2 B-frags

        // ======== row A: stage 1 (runs under row B's DRAM latency) ========
#pragma unroll
        for (int mt = 0; mt < 2; mt++)
#pragma unroll
            for (int kt = 0; kt < 2; kt++) {
                float4 u = xvA[mt][kt][0], v = xvA[mt][kt][1];
                split2(u.x, u.y, XAh[mt][kt][0], XAl[mt][kt][0]);
                split2(v.x, v.y, XAh[mt][kt][1], XAl[mt][kt][1]);
                split2(u.z, u.w, XAh[mt][kt][2], XAl[mt][kt][2]);
                split2(v.z, v.w, XAh[mt][kt][3], XAl[mt][kt][3]);
            }
#pragma unroll
        for (int i = 0; i < 32; i++) acc[i] = 0.f;
#pragma unroll
        for (int kt = 0; kt < 2; kt++)
#pragma unroll
            for (int mt = 0; mt < 2; mt++)
#pragma unroll
                for (int nt = 0; nt < 4; nt++) {
                    float* c = &acc[(mt * 4 + nt) * 4];
                    mma_bf16(c, XAh[mt][kt], w1Bh[kt][nt]);
                    mma_bf16(c, XAh[mt][kt], w1Bl[kt][nt]);
                    mma_bf16(c, XAl[mt][kt], w1Bh[kt][nt]);
                }
#pragma unroll
        for (int kt = 0; kt < 2; kt++)
#pragma unroll
            for (int nt = 0; nt < 4; nt++) {
                float* c = &acc[(kt * 4 + nt) * 4];
                u32 h01, l01, h23, l23;
                split2(c[0], c[1], h01, l01);
                split2(c[2], c[3], h23, l23);
                TAh[kt][nt][0] = movm(h01);
                TAh[kt][nt][1] = movm(h23);
                TAl[kt][nt][0] = movm(l01);
                TAl[kt][nt][1] = movm(l23);
            }

        // ======== row B: stage 1 ========
#pragma unroll
        for (int mt = 0; mt < 2; mt++)
#pragma unroll
            for (int kt = 0; kt < 2; kt++) {
                float4 u = xvB[mt][kt][0], v = xvB[mt][kt][1];
                split2(u.x, u.y, XAh[mt][kt][0], XAl[mt][kt][0]);
                split2(v.x, v.y, XAh[mt][kt][1], XAl[mt][kt][1]);
                split2(u.z, u.w, XAh[mt][kt][2], XAl[mt][kt][2]);
                split2(v.z, v.w, XAh[mt][kt][3], XAl[mt][kt][3]);
            }
#pragma unroll
        for (int i = 0; i < 32; i++) acc[i] = 0.f;
#pragma unroll
        for (int kt = 0; kt < 2; kt++)
#pragma unroll
            for (int mt = 0; mt < 2; mt++)
#pragma unroll
                for (int nt = 0; nt < 4; nt++) {
                    float* c = &acc[(mt * 4 + nt) * 4];
                    mma_bf16(c, XAh[mt][kt], w1Bh[kt][nt]);
                    mma_bf16(c, XAh[mt][kt], w1Bl[kt][nt]);
                    mma_bf16(c, XAl[mt][kt], w1Bh[kt][nt]);
                }
#pragma unroll
        for (int kt = 0; kt < 2; kt++)
#pragma unroll
            for (int nt = 0; nt < 4; nt++) {
                float* c = &acc[(kt * 4 + nt) * 4];
                u32 h01, l01, h23, l23;
                split2(c[0], c[1], h01, l01);
                split2(c[2], c[3], h23, l23);
                TBh[kt][nt][0] = movm(h01);
                TBh[kt][nt][1] = movm(h23);
                TBl[kt][nt][0] = movm(l01);
                TBl[kt][nt][1] = movm(l23);
            }

        // ======== row A: stage 2 + store ========
        float acc2[32];
#pragma unroll
        for (int t = 0; t < 8; t++) {
            float4 b4 = pbias4[t * 32 + lane];
            acc2[t*4+0] = b4.x; acc2[t*4+1] = b4.y;
            acc2[t*4+2] = b4.z; acc2[t*4+3] = b4.w;
        }
#pragma unroll
        for (int kt = 0; kt < 2; kt++)
#pragma unroll
            for (int mt = 0; mt < 2; mt++)
#pragma unroll
                for (int nt = 0; nt < 4; nt++) {
                    float* c = &acc2[(mt * 4 + nt) * 4];
                    mma_bf16(c, w2Ah[mt][kt], TAh[kt][nt]);
                    mma_bf16(c, w2Ah[mt][kt], TAl[kt][nt]);
                    mma_bf16(c, w2Al[mt][kt], TAh[kt][nt]);
                }
        {
            float* ob = out + (size_t)(2 * p) * 1024;
#pragma unroll
            for (int mt = 0; mt < 2; mt++)
#pragma unroll
                for (int h = 0; h < 2; h++) {
                    int base = (16 * mt + 8 * h + lq) * 32 + 8 * lr;
                    *(float4*)(ob + base) =
                        make_float4(acc2[(mt*4+0)*4+2*h], acc2[(mt*4+0)*4+2*h+1],
                                    acc2[(mt*4+1)*4+2*h], acc2[(mt*4+1)*4+2*h+1]);
                    *(float4*)(ob + base + 4) =
                        make_float4(acc2[(mt*4+2)*4+2*h], acc2[(mt*4+2)*4+2*h+1],
                                    acc2[(mt*4+3)*4+2*h], acc2[(mt*4+3)*4+2*h+1]);
                }
        }

        // ======== row B: stage 2 + store ========
#pragma unroll
        for (int t = 0; t < 8; t++) {
            float4 b4 = pbias4[t * 32 + lane];
            acc2[t*4+0] = b4.x; acc2[t*4+1] = b4.y;
            acc2[t*4+2] = b4.z; acc2[t*4+3] = b4.w;
        }
#pragma unroll
        for (int kt = 0; kt < 2; kt++)
#pragma unroll
            for (int mt = 0; mt < 2; mt++)
#pragma unroll
                for (int nt = 0; nt < 4; nt++) {
                    float* c = &acc2[(mt * 4 + nt) * 4];
                    mma_bf16(c, w2Ah[mt][kt], TBh[kt][nt]);
                    mma_bf16(c, w2Ah[mt][kt], TBl[kt][nt]);
                    mma_bf16(c, w2Al[mt][kt], TBh[kt][nt]);
                }
        {
            float* ob = out + (size_t)(2 * p + 1) * 1024;
#pragma unroll
            for (int mt = 0; mt < 2; mt++)
#pragma unroll
                for (int h = 0; h < 2; h++) {
                    int base = (16 * mt + 8 * h + lq) * 32 + 8 * lr;
                    *(float4*)(ob + base) =
                        make_float4(acc2[(mt*4+0)*4+2*h], acc2[(mt*4+0)*4+2*h+1],
                                    acc2[(mt*4+1)*4+2*h], acc2[(mt*4+1)*4+2*h+1]);
                    *(float4*)(ob + base + 4) =
                        make_float4(acc2[(mt*4+2)*4+2*h], acc2[(mt*4+2)*4+2*h+1],
                                    acc2[(mt*4+3)*4+2*h], acc2[(mt*4+3)*4+2*h+1]);
                }
        }
    }
}

extern "C" void kernel_launch(void* const* d_in, const int* in_sizes, int n_in,
                              void* d_out, int out_size) {
    const float* x    = (const float*)d_in[0];
    const float* w1   = (const float*)d_in[1];
    const float* w2   = (const float*)d_in[2];
    const float* bias = (const float*)d_in[3];
    float* out        = (float*)d_out;

    int rows = in_sizes[0] / 1024;    // 65536

    int grid = 444;                   // 3 CTAs/SM, grid-stride over row pairs
    int maxg = ((rows >> 1) + NW - 1) / NW;
    if (grid > maxg) grid = maxg;
    kron_mma9_kernel<<<grid, NW * 32>>>(x, w1, w2, bias, out, rows);
}

// round 14
// speedup vs baseline: 1.0669x; 1.0669x over previous
#include <cuda_runtime.h>
#include <cuda_bf16.h>
#include <cstdint>

// y[m, i2*32+i1] = sum_{j2,j1} x[m,j2*32+j1] * W2[i2,j2] * W1[i1,j1] + bias
// Stage1: T = X @ W1^T (sigma k-permuted A-frags; W1^T B-frags in regs)
// Stage2: G = W2 @ T   (W2 A-frags in regs; T via movmatrix)
// R14: cp.async double-buffered per-warp X staging (zero register cost
// latency hiding; XOR-swizzled 128B rows -> conflict-free LDS.128).
// mma.sync.m16n8k16 bf16, fp32 accuracy via 3-term hi/lo split.

typedef unsigned int u32;

#define RS 80                 // weight staging row stride (bytes)
#define NW 4                  // warps per CTA

__shared__ __align__(16) char swts[10240];     // W1h@0 W1l@2560 W2h@5120 W2l@7680
__shared__ __align__(16) float4 pbias4[256];   // [t][lane] tau/frag-permuted bias
__shared__ __align__(16) char sxbuf[NW][2][4096];  // per-warp double buffer

__device__ __forceinline__ u32 smem_u32(const void* p) {
    u32 a;
    asm("{ .reg .u64 t; cvta.to.shared.u64 t, %1; cvt.u32.u64 %0, t; }"
        : "=r"(a) : "l"(p));
    return a;
}
__device__ __forceinline__ void ldm_x4(u32* r, u32 addr) {
    asm volatile("ldmatrix.sync.aligned.m8n8.x4.shared.b16 {%0,%1,%2,%3}, [%4];"
                 : "=r"(r[0]), "=r"(r[1]), "=r"(r[2]), "=r"(r[3]) : "r"(addr));
}
__device__ __forceinline__ u32 movm(u32 v) {
    u32 d;
    asm("movmatrix.sync.aligned.m8n8.trans.b16 %0, %1;" : "=r"(d) : "r"(v));
    return d;
}
__device__ __forceinline__ void mma_bf16(float* c, const u32* a, const u32* b) {
    asm volatile(
        "mma.sync.aligned.m16n8k16.row.col.f32.bf16.bf16.f32 "
        "{%0,%1,%2,%3}, {%4,%5,%6,%7}, {%8,%9}, {%0,%1,%2,%3};"
        : "+f"(c[0]), "+f"(c[1]), "+f"(c[2]), "+f"(c[3])
        : "r"(a[0]), "r"(a[1]), "r"(a[2]), "r"(a[3]), "r"(b[0]), "r"(b[1]));
}
// h = bf16x2(a -> low half, b -> high half); l = residuals
__device__ __forceinline__ void split2(float a, float b, u32& h, u32& l) {
    asm("cvt.rn.bf16x2.f32 %0, %1, %2;" : "=r"(h) : "f"(b), "f"(a));
    float ha = __uint_as_float(h << 16);
    float hb = __uint_as_float(h & 0xFFFF0000u);
    float ra = a - ha, rb = b - hb;
    asm("cvt.rn.bf16x2.f32 %0, %1, %2;" : "=r"(l) : "f"(rb), "f"(ra));
}
// split 32 floats, store hi/lo 64B rows at rowPtr / rowPtr+2560
__device__ __forceinline__ void split_store_row(char* rowPtr, const float* v) {
    u32 hw[16], lw[16];
#pragma unroll
    for (int p = 0; p < 16; p++) split2(v[2 * p], v[2 * p + 1], hw[p], lw[p]);
#pragma unroll
    for (int c = 0; c < 4; c++) {
        *(uint4*)(rowPtr + c * 16) =
            make_uint4(hw[4 * c], hw[4 * c + 1], hw[4 * c + 2], hw[4 * c + 3]);
        *(uint4*)(rowPtr + 2560 + c * 16) =
            make_uint4(lw[4 * c], lw[4 * c + 1], lw[4 * c + 2], lw[4 * c + 3]);
    }
}
// sigma: frag k-pos (within 16-block) -> physical col (within 16-block)
__device__ __forceinline__ int sigma16(int k) {
    return 4 * ((k & 7) >> 1) + 2 * (k >> 3) + (k & 1);
}
// tau: frag n-pos -> physical i1 col (involution, global 0..31)
__device__ __forceinline__ int tau32(int n) {
    return 8 * ((n & 7) >> 1) + 2 * (n >> 3) + (n & 1);
}
__device__ __forceinline__ float4 lds128(u32 addr) {
    float4 v;
    asm volatile("ld.shared.v4.f32 {%0,%1,%2,%3}, [%4];"
                 : "=f"(v.x), "=f"(v.y), "=f"(v.z), "=f"(v.w) : "r"(addr));
    return v;
}
#define CP_COMMIT() asm volatile("cp.async.commit_group;" ::: "memory")
#define CP_WAIT1()  asm volatile("cp.async.wait_group 1;" ::: "memory")

// Fill one 4KB stage with row xb: 8 cp.async, each covers 4 full rows
// (fully coalesced 512B gmem reads). Swizzle: chunk_phys = cc ^ key(row&7).
__device__ __forceinline__ void fill_stage(u32 dstBase, const float* xb,
                                           int lane) {
    int rr = lane >> 3;                 // 0..3 sub-row
    int cc = lane & 7;                  // 16B chunk
    int key_e = ((rr & 1) << 2) | (rr >> 1);      // key for even q
    u32 blane = (u32)(rr * 128 + ((cc ^ key_e) << 4));
    const char* src = (const char*)xb + rr * 128 + cc * 16;
#pragma unroll
    for (int q = 0; q < 8; q++) {       // rows 4q..4q+3; odd q: key ^= 2
        u32 dst = dstBase + q * 512 + (blane ^ ((u32)(q & 1) << 5));
        asm volatile("cp.async.cg.shared.global [%0], [%1], 16;"
                     :: "r"(dst), "l"(src + q * 512) : "memory");
    }
}

__global__ void __launch_bounds__(NW * 32, 4)
kron_mma10_kernel(const float* __restrict__ x,
                  const float* __restrict__ w1,
                  const float* __restrict__ w2,
                  const float* __restrict__ bias,
                  float* __restrict__ out,
                  int rows)
{
    const int tid  = threadIdx.x;
    const int lane = tid & 31;
    const int wrp  = tid >> 5;

    const int lq = lane >> 2;           // frag row within 8-block
    const int lr = lane & 3;            // quad index r

    const u32 laneOff = ((lane & 7) + 8 * ((lane >> 3) & 1)) * RS +
                        ((lane >> 4) << 4);

    // ---- one-time staging ----
    if (wrp == 0) {
        // M1[nu][c] = W1[tau(nu)][16*(c>>4)+sigma(c&15)]  (lane = nu)
        float v[32];
        const float* wrow = w1 + tau32(lane) * 32;
#pragma unroll
        for (int c = 0; c < 32; c++)
            v[c] = wrow[16 * (c >> 4) + sigma16(c & 15)];
        split_store_row(swts + 0 + lane * RS, v);
    } else if (wrp == 1) {
        // M2[i2][j2] = W2 row-major
        float v[32];
        const float4* r = (const float4*)(w2 + lane * 32);
#pragma unroll
        for (int q = 0; q < 8; q++) {
            float4 t = r[q];
            v[4*q] = t.x; v[4*q+1] = t.y; v[4*q+2] = t.z; v[4*q+3] = t.w;
        }
        split_store_row(swts + 5120 + lane * RS, v);
    }
    for (int t = wrp; t < 8; t += NW) {
        int mt = t >> 2, nt = t & 3;
        int row = 16 * mt + lq;
        int col = 8 * lr + 2 * nt;
        pbias4[t * 32 + lane] =
            make_float4(bias[row * 32 + col], bias[row * 32 + col + 1],
                        bias[(row + 8) * 32 + col], bias[(row + 8) * 32 + col + 1]);
    }
    __syncthreads();

    // ---- invariant weight fragments in registers ----
    const u32 s0 = smem_u32(swts);
    u32 w1Bh[2][4][2], w1Bl[2][4][2];
#pragma unroll
    for (int a = 0; a < 2; a++)
#pragma unroll
        for (int b = 0; b < 2; b++) {
            u32 r[4];
            ldm_x4(r, s0 + 0 + a * (16 * RS) + b * 32 + laneOff);
            w1Bh[b][2*a][0] = r[0]; w1Bh[b][2*a+1][0] = r[1];
            w1Bh[b][2*a][1] = r[2]; w1Bh[b][2*a+1][1] = r[3];
            ldm_x4(r, s0 + 2560 + a * (16 * RS) + b * 32 + laneOff);
            w1Bl[b][2*a][0] = r[0]; w1Bl[b][2*a+1][0] = r[1];
            w1Bl[b][2*a][1] = r[2]; w1Bl[b][2*a+1][1] = r[3];
        }
    u32 w2Ah[2][2][4], w2Al[2][2][4];
#pragma unroll
    for (int mt = 0; mt < 2; mt++)
#pragma unroll
        for (int kt = 0; kt < 2; kt++) {
            ldm_x4(w2Ah[mt][kt], s0 + 5120 + mt * (16 * RS) + kt * 32 + laneOff);
            ldm_x4(w2Al[mt][kt], s0 + 7680 + mt * (16 * RS) + kt * 32 + laneOff);
        }
    __syncthreads();

    const int gw = blockIdx.x * NW + wrp;
    const int nw = gridDim.x * NW;
    const u32 sxb = smem_u32(&sxbuf[wrp][0][0]);

    // per-lane read swizzle: key(lq); chunk offsets for kt=0 (kt=1: ^64)
    const int rko = ((lq & 1) << 2) | (lq >> 1);
    const u32 rchunk = (u32)((lr ^ rko) << 4);

    // ---- pipeline prologue: fill stages 0 and 1 ----
    if (gw < rows)       fill_stage(sxb,        x + (size_t)gw * 1024, lane);
    CP_COMMIT();
    if (gw + nw < rows)  fill_stage(sxb + 4096, x + (size_t)(gw + nw) * 1024, lane);
    CP_COMMIT();

    u32 stg = 0;
    for (int m = gw; m < rows; m += nw) {
        CP_WAIT1();              // current stage's fill complete
        __syncwarp();

        // ---- read X from smem stage (8 conflict-free LDS.128) ----
        const u32 sb = sxb + stg * 4096;
        float4 xv[2][2][2];   // [mt][kt][h]
#pragma unroll
        for (int mt = 0; mt < 2; mt++)
#pragma unroll
            for (int kt = 0; kt < 2; kt++) {
                u32 rowoff = (u32)((16 * mt + lq) * 128);
                u32 coff = rchunk ^ ((u32)kt << 6);
                xv[mt][kt][0] = lds128(sb + rowoff + coff);
                xv[mt][kt][1] = lds128(sb + rowoff + 1024 + coff);  // +8 rows
            }

        // ---- split into A-frags ----
        u32 XAh[2][2][4], XAl[2][2][4];
#pragma unroll
        for (int mt = 0; mt < 2; mt++)
#pragma unroll
            for (int kt = 0; kt < 2; kt++) {
                float4 u = xv[mt][kt][0], v = xv[mt][kt][1];
                split2(u.x, u.y, XAh[mt][kt][0], XAl[mt][kt][0]);
                split2(v.x, v.y, XAh[mt][kt][1], XAl[mt][kt][1]);
                split2(u.z, u.w, XAh[mt][kt][2], XAl[mt][kt][2]);
                split2(v.z, v.w, XAh[mt][kt][3], XAl[mt][kt][3]);
            }
        __syncwarp();            // all lanes done reading stage

        // ---- refill this stage with row m+2nw (async, runs under compute)
        if (m + 2 * nw < rows)
            fill_stage(sb, x + (size_t)(m + 2 * nw) * 1024, lane);
        CP_COMMIT();             // empty group if no fill (keeps bookkeeping)

        // ---- stage 1: T = X @ W1^T (3-term split) ----
        float acc[32];
#pragma unroll
        for (int i = 0; i < 32; i++) acc[i] = 0.f;
#pragma unroll
        for (int kt = 0; kt < 2; kt++)
#pragma unroll
            for (int mt = 0; mt < 2; mt++)
#pragma unroll
                for (int nt = 0; nt < 4; nt++) {
                    float* c = &acc[(mt * 4 + nt) * 4];
                    mma_bf16(c, XAh[mt][kt], w1Bh[kt][nt]);
                    mma_bf16(c, XAh[mt][kt], w1Bl[kt][nt]);
                    mma_bf16(c, XAl[mt][kt], w1Bh[kt][nt]);
                }

        // ---- T c-frags -> stage-2 B-frags via movmatrix ----
        u32 TBh[2][4][2], TBl[2][4][2];
#pragma unroll
        for (int kt = 0; kt < 2; kt++)
#pragma unroll
            for (int nt = 0; nt < 4; nt++) {
                float* c = &acc[(kt * 4 + nt) * 4];
                u32 h01, l01, h23, l23;
                split2(c[0], c[1], h01, l01);
                split2(c[2], c[3], h23, l23);
                TBh[kt][nt][0] = movm(h01);
                TBh[kt][nt][1] = movm(h23);
                TBl[kt][nt][0] = movm(l01);
                TBl[kt][nt][1] = movm(l23);
            }

        // ---- stage 2: G = W2 @ T, acc init = bias (8 LDS.128) ----
        float acc2[32];
#pragma unroll
        for (int t = 0; t < 8; t++) {
            float4 b4 = pbias4[t * 32 + lane];
            acc2[t*4+0] = b4.x; acc2[t*4+1] = b4.y;
            acc2[t*4+2] = b4.z; acc2[t*4+3] = b4.w;
        }
#pragma unroll
        for (int kt = 0; kt < 2; kt++)
#pragma unroll
            for (int mt = 0; mt < 2; mt++)
#pragma unroll
                for (int nt = 0; nt < 4; nt++) {
                    float* c = &acc2[(mt * 4 + nt) * 4];
                    mma_bf16(c, w2Ah[mt][kt], TBh[kt][nt]);
                    mma_bf16(c, w2Ah[mt][kt], TBl[kt][nt]);
                    mma_bf16(c, w2Al[mt][kt], TBh[kt][nt]);
                }

        // ---- store: tau gives each lane 32B contiguous per row -> STG.128
        float* ob = out + (size_t)m * 1024;
#pragma unroll
        for (int mt = 0; mt < 2; mt++)
#pragma unroll
            for (int h = 0; h < 2; h++) {
                int base = (16 * mt + 8 * h + lq) * 32 + 8 * lr;
                *(float4*)(ob + base) =
                    make_float4(acc2[(mt*4+0)*4+2*h], acc2[(mt*4+0)*4+2*h+1],
                                acc2[(mt*4+1)*4+2*h], acc2[(mt*4+1)*4+2*h+1]);
                *(float4*)(ob + base + 4) =
                    make_float4(acc2[(mt*4+2)*4+2*h], acc2[(mt*4+2)*4+2*h+1],
                                acc2[(mt*4+3)*4+2*h], acc2[(mt*4+3)*4+2*h+1]);
            }

        stg ^= 1;
    }
}

extern "C" void kernel_launch(void* const* d_in, const int* in_sizes, int n_in,
                              void* d_out, int out_size) {
    const float* x    = (const float*)d_in[0];
    const float* w1   = (const float*)d_in[1];
    const float* w2   = (const float*)d_in[2];
    const float* bias = (const float*)d_in[3];
    float* out        = (float*)d_out;

    int rows = in_sizes[0] / 1024;    // 65536

    int grid = 592;                   // 4 CTAs/SM, grid-stride persistent
    int maxg = (rows + NW - 1) / NW;
    if (grid > maxg) grid = maxg;
    kron_mma10_kernel<<<grid, NW * 32>>>(x, w1, w2, bias, out, rows);
}

// round 15
// speedup vs baseline: 1.1142x; 1.0442x over previous
#include <cuda_runtime.h>
#include <cuda_bf16.h>
#include <cstdint>

// y[m, i2*32+i1] = sum_{j2,j1} x[m,j2*32+j1] * W2[i2,j2] * W1[i1,j1] + bias
// Stage1: T = X @ W1^T (sigma k-permuted A-frags from gmem; W1^T hi-frags
//         in regs, W1^T lo-frags reloaded per row from smem)
// Stage2: G = W2 @ T   (W2 hi-frags in regs, lo reloaded; T via movmatrix)
// R15: register diet -> <=102 regs -> 5 CTAs/SM = 20 warps (+25% vs R9).
// Evidence: perf tracks warp count (16w: 94.8-101us, 12w: 101-111us).
// mma.sync.m16n8k16 bf16, fp32 accuracy via 3-term hi/lo split.

typedef unsigned int u32;

#define RS 80                 // weight staging row stride (bytes)
#define NW 4                  // warps per CTA

__shared__ __align__(16) char swts[10240];     // W1h@0 W1l@2560 W2h@5120 W2l@7680
__shared__ __align__(16) float4 pbias4[256];   // [t][lane] tau/frag-permuted bias

__device__ __forceinline__ u32 smem_u32(const void* p) {
    u32 a;
    asm("{ .reg .u64 t; cvta.to.shared.u64 t, %1; cvt.u32.u64 %0, t; }"
        : "=r"(a) : "l"(p));
    return a;
}
__device__ __forceinline__ void ldm_x4(u32* r, u32 addr) {
    asm volatile("ldmatrix.sync.aligned.m8n8.x4.shared.b16 {%0,%1,%2,%3}, [%4];"
                 : "=r"(r[0]), "=r"(r[1]), "=r"(r[2]), "=r"(r[3]) : "r"(addr));
}
__device__ __forceinline__ u32 movm(u32 v) {
    u32 d;
    asm("movmatrix.sync.aligned.m8n8.trans.b16 %0, %1;" : "=r"(d) : "r"(v));
    return d;
}
__device__ __forceinline__ void mma_bf16(float* c, const u32* a, const u32* b) {
    asm volatile(
        "mma.sync.aligned.m16n8k16.row.col.f32.bf16.bf16.f32 "
        "{%0,%1,%2,%3}, {%4,%5,%6,%7}, {%8,%9}, {%0,%1,%2,%3};"
        : "+f"(c[0]), "+f"(c[1]), "+f"(c[2]), "+f"(c[3])
        : "r"(a[0]), "r"(a[1]), "r"(a[2]), "r"(a[3]), "r"(b[0]), "r"(b[1]));
}
// h = bf16x2(a -> low half, b -> high half); l = residuals
__device__ __forceinline__ void split2(float a, float b, u32& h, u32& l) {
    asm("cvt.rn.bf16x2.f32 %0, %1, %2;" : "=r"(h) : "f"(b), "f"(a));
    float ha = __uint_as_float(h << 16);
    float hb = __uint_as_float(h & 0xFFFF0000u);
    float ra = a - ha, rb = b - hb;
    asm("cvt.rn.bf16x2.f32 %0, %1, %2;" : "=r"(l) : "f"(rb), "f"(ra));
}
// split 32 floats, store hi/lo 64B rows at rowPtr / rowPtr+2560
__device__ __forceinline__ void split_store_row(char* rowPtr, const float* v) {
    u32 hw[16], lw[16];
#pragma unroll
    for (int p = 0; p < 16; p++) split2(v[2 * p], v[2 * p + 1], hw[p], lw[p]);
#pragma unroll
    for (int c = 0; c < 4; c++) {
        *(uint4*)(rowPtr + c * 16) =
            make_uint4(hw[4 * c], hw[4 * c + 1], hw[4 * c + 2], hw[4 * c + 3]);
        *(uint4*)(rowPtr + 2560 + c * 16) =
            make_uint4(lw[4 * c], lw[4 * c + 1], lw[4 * c + 2], lw[4 * c + 3]);
    }
}
// sigma: frag k-pos (within 16-block) -> physical col (within 16-block)
__device__ __forceinline__ int sigma16(int k) {
    return 4 * ((k & 7) >> 1) + 2 * (k >> 3) + (k & 1);
}
// tau: frag n-pos -> physical i1 col (involution, global 0..31)
__device__ __forceinline__ int tau32(int n) {
    return 8 * ((n & 7) >> 1) + 2 * (n >> 3) + (n & 1);
}

__global__ void __launch_bounds__(NW * 32, 5)
kron_mma11_kernel(const float* __restrict__ x,
                  const float* __restrict__ w1,
                  const float* __restrict__ w2,
                  const float* __restrict__ bias,
                  float* __restrict__ out,
                  int rows)
{
    const int tid  = threadIdx.x;
    const int lane = tid & 31;
    const int wrp  = tid >> 5;

    const int lq = lane >> 2;           // frag row within 8-block
    const int lr = lane & 3;            // quad index r

    const u32 laneOff = ((lane & 7) + 8 * ((lane >> 3) & 1)) * RS +
                        ((lane >> 4) << 4);

    // ---- one-time staging (all four weight planes into smem) ----
    if (wrp == 0) {
        // M1[nu][c] = W1[tau(nu)][16*(c>>4)+sigma(c&15)]  (lane = nu)
        float v[32];
        const float* wrow = w1 + tau32(lane) * 32;
#pragma unroll
        for (int c = 0; c < 32; c++)
            v[c] = wrow[16 * (c >> 4) + sigma16(c & 15)];
        split_store_row(swts + 0 + lane * RS, v);
    } else if (wrp == 1) {
        // M2[i2][j2] = W2 row-major
        float v[32];
        const float4* r = (const float4*)(w2 + lane * 32);
#pragma unroll
        for (int q = 0; q < 8; q++) {
            float4 t = r[q];
            v[4*q] = t.x; v[4*q+1] = t.y; v[4*q+2] = t.z; v[4*q+3] = t.w;
        }
        split_store_row(swts + 5120 + lane * RS, v);
    }
    // pbias4[t=mt*4+nt][lane]: physical (row 16mt+lq(+8), col 8*lr+2*nt, +1)
    for (int t = wrp; t < 8; t += NW) {
        int mt = t >> 2, nt = t & 3;
        int row = 16 * mt + lq;
        int col = 8 * lr + 2 * nt;
        pbias4[t * 32 + lane] =
            make_float4(bias[row * 32 + col], bias[row * 32 + col + 1],
                        bias[(row + 8) * 32 + col], bias[(row + 8) * 32 + col + 1]);
    }
    __syncthreads();

    // ---- persistent HI weight fragments only (32 regs) ----
    const u32 s0 = smem_u32(swts);
    u32 w1Bh[2][4][2];                  // [kt][nt][reg]
#pragma unroll
    for (int a = 0; a < 2; a++)
#pragma unroll
        for (int b = 0; b < 2; b++) {
            u32 r[4];
            ldm_x4(r, s0 + 0 + a * (16 * RS) + b * 32 + laneOff);
            w1Bh[b][2*a][0] = r[0]; w1Bh[b][2*a+1][0] = r[1];
            w1Bh[b][2*a][1] = r[2]; w1Bh[b][2*a+1][1] = r[3];
        }
    u32 w2Ah[2][2][4];                  // [mt][kt][4]
#pragma unroll
    for (int mt = 0; mt < 2; mt++)
#pragma unroll
        for (int kt = 0; kt < 2; kt++)
            ldm_x4(w2Ah[mt][kt], s0 + 5120 + mt * (16 * RS) + kt * 32 + laneOff);

    const int gw = blockIdx.x * NW + wrp;
    const int nw = gridDim.x * NW;

    for (int m = gw; m < rows; m += nw) {
        const float* xb = x + (size_t)m * 1024;
        float acc[32];
#pragma unroll
        for (int i = 0; i < 32; i++) acc[i] = 0.f;

        // ---- stage 1, kt-blocked (X liveness halved) ----
#pragma unroll
        for (int kt = 0; kt < 2; kt++) {
            // 4 LDG.128 for this k-half; sigma makes lane's float4 = its frag
            float4 u0, u1, u2, u3;
            {
                int base = lq * 32 + 16 * kt + 4 * lr;
                u0 = *(const float4*)(xb + base);          // mt=0 rows lq
                u1 = *(const float4*)(xb + base + 256);    // mt=0 rows lq+8
                u2 = *(const float4*)(xb + base + 512);    // mt=1
                u3 = *(const float4*)(xb + base + 768);
            }
            u32 XAh[2][4], XAl[2][4];
            split2(u0.x, u0.y, XAh[0][0], XAl[0][0]);
            split2(u1.x, u1.y, XAh[0][1], XAl[0][1]);
            split2(u0.z, u0.w, XAh[0][2], XAl[0][2]);
            split2(u1.z, u1.w, XAh[0][3], XAl[0][3]);
            split2(u2.x, u2.y, XAh[1][0], XAl[1][0]);
            split2(u3.x, u3.y, XAh[1][1], XAl[1][1]);
            split2(u2.z, u2.w, XAh[1][2], XAl[1][2]);
            split2(u3.z, u3.w, XAh[1][3], XAl[1][3]);

            // pass A: Ah x Bh ; pass C: Al x Bh (persistent w1Bh)
#pragma unroll
            for (int mt = 0; mt < 2; mt++)
#pragma unroll
                for (int nt = 0; nt < 4; nt++) {
                    float* c = &acc[(mt * 4 + nt) * 4];
                    mma_bf16(c, XAh[mt], w1Bh[kt][nt]);
                    mma_bf16(c, XAl[mt], w1Bh[kt][nt]);
                }
            // pass B: Ah x Bl (w1 lo frags loaded transiently from smem)
#pragma unroll
            for (int a = 0; a < 2; a++) {
                u32 r[4];
                ldm_x4(r, s0 + 2560 + a * (16 * RS) + kt * 32 + laneOff);
                u32 b0[2] = { r[0], r[2] };   // nt = 2a
                u32 b1[2] = { r[1], r[3] };   // nt = 2a+1
#pragma unroll
                for (int mt = 0; mt < 2; mt++) {
                    mma_bf16(&acc[(mt * 4 + 2 * a) * 4],     XAh[mt], b0);
                    mma_bf16(&acc[(mt * 4 + 2 * a + 1) * 4], XAh[mt], b1);
                }
            }
        }

        // ---- stage 2, kt-blocked; acc halves die into TB frags ----
        float acc2[32];
#pragma unroll
        for (int t = 0; t < 8; t++) {
            float4 b4 = pbias4[t * 32 + lane];
            acc2[t*4+0] = b4.x; acc2[t*4+1] = b4.y;
            acc2[t*4+2] = b4.z; acc2[t*4+3] = b4.w;
        }
#pragma unroll
        for (int kt = 0; kt < 2; kt++) {
            // build this half's T B-frags via movmatrix (acc half dies)
            u32 TBh[4][2], TBl[4][2];
#pragma unroll
            for (int nt = 0; nt < 4; nt++) {
                float* c = &acc[(kt * 4 + nt) * 4];
                u32 h01, l01, h23, l23;
                split2(c[0], c[1], h01, l01);
                split2(c[2], c[3], h23, l23);
                TBh[nt][0] = movm(h01);
                TBh[nt][1] = movm(h23);
                TBl[nt][0] = movm(l01);
                TBl[nt][1] = movm(l23);
            }
            // passes A+B: persistent w2Ah x (TBh, TBl)
#pragma unroll
            for (int mt = 0; mt < 2; mt++)
#pragma unroll
                for (int nt = 0; nt < 4; nt++) {
                    float* c = &acc2[(mt * 4 + nt) * 4];
                    mma_bf16(c, w2Ah[mt][kt], TBh[nt]);
                    mma_bf16(c, w2Ah[mt][kt], TBl[nt]);
                }
            // pass C: transient w2 lo frags x TBh
#pragma unroll
            for (int mt = 0; mt < 2; mt++) {
                u32 al[4];
                ldm_x4(al, s0 + 7680 + mt * (16 * RS) + kt * 32 + laneOff);
#pragma unroll
                for (int nt = 0; nt < 4; nt++)
                    mma_bf16(&acc2[(mt * 4 + nt) * 4], al, TBh[nt]);
            }
        }

        // ---- store: tau gives each lane 32B contiguous per row -> STG.128
        float* ob = out + (size_t)m * 1024;
#pragma unroll
        for (int mt = 0; mt < 2; mt++)
#pragma unroll
            for (int h = 0; h < 2; h++) {
                int base = (16 * mt + 8 * h + lq) * 32 + 8 * lr;
                *(float4*)(ob + base) =
                    make_float4(acc2[(mt*4+0)*4+2*h], acc2[(mt*4+0)*4+2*h+1],
                                acc2[(mt*4+1)*4+2*h], acc2[(mt*4+1)*4+2*h+1]);
                *(float4*)(ob + base + 4) =
                    make_float4(acc2[(mt*4+2)*4+2*h], acc2[(mt*4+2)*4+2*h+1],
                                acc2[(mt*4+3)*4+2*h], acc2[(mt*4+3)*4+2*h+1]);
            }
    }
}

extern "C" void kernel_launch(void* const* d_in, const int* in_sizes, int n_in,
                              void* d_out, int out_size) {
    const float* x    = (const float*)d_in[0];
    const float* w1   = (const float*)d_in[1];
    const float* w2   = (const float*)d_in[2];
    const float* bias = (const float*)d_in[3];
    float* out        = (float*)d_out;

    int rows = in_sizes[0] / 1024;    // 65536

    int grid = 740;                   // 5 CTAs/SM (20 warps), grid-stride
    int maxg = (rows + NW - 1) / NW;
    if (grid > maxg) grid = maxg;
    kron_mma11_kernel<<<grid, NW * 32>>>(x, w1, w2, bias, out, rows);
}

// round 16
// speedup vs baseline: 1.1198x; 1.0051x over previous
#include <cuda_runtime.h>
#include <cuda_bf16.h>
#include <cstdint>

// y[m, i2*32+i1] = sum_{j2,j1} x[m,j2*32+j1] * W2[i2,j2] * W1[i1,j1] + bias
// Stage1: T = X @ W1^T (sigma k-permuted A-frags from gmem; W1^T hi-frags
//         in regs, W1^T lo-frags reloaded per row from smem)
// Stage2: G = W2 @ T   (W2 hi-frags in regs, lo reloaded; T via movmatrix)
// R16: R15 (96 regs, 5 CTAs/SM) + dynamic work stealing (per-warp atomic
// row counter, CHUNK=2) to remove cross-die CTA spread + 22/23-row tail.
// mma.sync.m16n8k16 bf16, fp32 accuracy via 3-term hi/lo split.

typedef unsigned int u32;

#define RS 80                 // weight staging row stride (bytes)
#define NW 4                  // warps per CTA
#define CHUNK 2               // rows per steal

__device__ u32 g_row_ctr;

__global__ void reset_ctr_kernel() { g_row_ctr = 0; }

__shared__ __align__(16) char swts[10240];     // W1h@0 W1l@2560 W2h@5120 W2l@7680
__shared__ __align__(16) float4 pbias4[256];   // [t][lane] tau/frag-permuted bias

__device__ __forceinline__ u32 smem_u32(const void* p) {
    u32 a;
    asm("{ .reg .u64 t; cvta.to.shared.u64 t, %1; cvt.u32.u64 %0, t; }"
        : "=r"(a) : "l"(p));
    return a;
}
__device__ __forceinline__ void ldm_x4(u32* r, u32 addr) {
    asm volatile("ldmatrix.sync.aligned.m8n8.x4.shared.b16 {%0,%1,%2,%3}, [%4];"
                 : "=r"(r[0]), "=r"(r[1]), "=r"(r[2]), "=r"(r[3]) : "r"(addr));
}
__device__ __forceinline__ u32 movm(u32 v) {
    u32 d;
    asm("movmatrix.sync.aligned.m8n8.trans.b16 %0, %1;" : "=r"(d) : "r"(v));
    return d;
}
__device__ __forceinline__ void mma_bf16(float* c, const u32* a, const u32* b) {
    asm volatile(
        "mma.sync.aligned.m16n8k16.row.col.f32.bf16.bf16.f32 "
        "{%0,%1,%2,%3}, {%4,%5,%6,%7}, {%8,%9}, {%0,%1,%2,%3};"
        : "+f"(c[0]), "+f"(c[1]), "+f"(c[2]), "+f"(c[3])
        : "r"(a[0]), "r"(a[1]), "r"(a[2]), "r"(a[3]), "r"(b[0]), "r"(b[1]));
}
// h = bf16x2(a -> low half, b -> high half); l = residuals
__device__ __forceinline__ void split2(float a, float b, u32& h, u32& l) {
    asm("cvt.rn.bf16x2.f32 %0, %1, %2;" : "=r"(h) : "f"(b), "f"(a));
    float ha = __uint_as_float(h << 16);
    float hb = __uint_as_float(h & 0xFFFF0000u);
    float ra = a - ha, rb = b - hb;
    asm("cvt.rn.bf16x2.f32 %0, %1, %2;" : "=r"(l) : "f"(rb), "f"(ra));
}
// split 32 floats, store hi/lo 64B rows at rowPtr / rowPtr+2560
__device__ __forceinline__ void split_store_row(char* rowPtr, const float* v) {
    u32 hw[16], lw[16];
#pragma unroll
    for (int p = 0; p < 16; p++) split2(v[2 * p], v[2 * p + 1], hw[p], lw[p]);
#pragma unroll
    for (int c = 0; c < 4; c++) {
        *(uint4*)(rowPtr + c * 16) =
            make_uint4(hw[4 * c], hw[4 * c + 1], hw[4 * c + 2], hw[4 * c + 3]);
        *(uint4*)(rowPtr + 2560 + c * 16) =
            make_uint4(lw[4 * c], lw[4 * c + 1], lw[4 * c + 2], lw[4 * c + 3]);
    }
}
// sigma: frag k-pos (within 16-block) -> physical col (within 16-block)
__device__ __forceinline__ int sigma16(int k) {
    return 4 * ((k & 7) >> 1) + 2 * (k >> 3) + (k & 1);
}
// tau: frag n-pos -> physical i1 col (involution, global 0..31)
__device__ __forceinline__ int tau32(int n) {
    return 8 * ((n & 7) >> 1) + 2 * (n >> 3) + (n & 1);
}

__global__ void __launch_bounds__(NW * 32, 5)
kron_mma12_kernel(const float* __restrict__ x,
                  const float* __restrict__ w1,
                  const float* __restrict__ w2,
                  const float* __restrict__ bias,
                  float* __restrict__ out,
                  int rows)
{
    const int tid  = threadIdx.x;
    const int lane = tid & 31;
    const int wrp  = tid >> 5;

    const int lq = lane >> 2;           // frag row within 8-block
    const int lr = lane & 3;            // quad index r

    const u32 laneOff = ((lane & 7) + 8 * ((lane >> 3) & 1)) * RS +
                        ((lane >> 4) << 4);

    // ---- one-time staging (all four weight planes into smem) ----
    if (wrp == 0) {
        // M1[nu][c] = W1[tau(nu)][16*(c>>4)+sigma(c&15)]  (lane = nu)
        float v[32];
        const float* wrow = w1 + tau32(lane) * 32;
#pragma unroll
        for (int c = 0; c < 32; c++)
            v[c] = wrow[16 * (c >> 4) + sigma16(c & 15)];
        split_store_row(swts + 0 + lane * RS, v);
    } else if (wrp == 1) {
        // M2[i2][j2] = W2 row-major
        float v[32];
        const float4* r = (const float4*)(w2 + lane * 32);
#pragma unroll
        for (int q = 0; q < 8; q++) {
            float4 t = r[q];
            v[4*q] = t.x; v[4*q+1] = t.y; v[4*q+2] = t.z; v[4*q+3] = t.w;
        }
        split_store_row(swts + 5120 + lane * RS, v);
    }
    // pbias4[t=mt*4+nt][lane]: physical (row 16mt+lq(+8), col 8*lr+2*nt, +1)
    for (int t = wrp; t < 8; t += NW) {
        int mt = t >> 2, nt = t & 3;
        int row = 16 * mt + lq;
        int col = 8 * lr + 2 * nt;
        pbias4[t * 32 + lane] =
            make_float4(bias[row * 32 + col], bias[row * 32 + col + 1],
                        bias[(row + 8) * 32 + col], bias[(row + 8) * 32 + col + 1]);
    }
    __syncthreads();

    // ---- persistent HI weight fragments only (32 regs) ----
    const u32 s0 = smem_u32(swts);
    u32 w1Bh[2][4][2];                  // [kt][nt][reg]
#pragma unroll
    for (int a = 0; a < 2; a++)
#pragma unroll
        for (int b = 0; b < 2; b++) {
            u32 r[4];
            ldm_x4(r, s0 + 0 + a * (16 * RS) + b * 32 + laneOff);
            w1Bh[b][2*a][0] = r[0]; w1Bh[b][2*a+1][0] = r[1];
            w1Bh[b][2*a][1] = r[2]; w1Bh[b][2*a+1][1] = r[3];
        }
    u32 w2Ah[2][2][4];                  // [mt][kt][4]
#pragma unroll
    for (int mt = 0; mt < 2; mt++)
#pragma unroll
        for (int kt = 0; kt < 2; kt++)
            ldm_x4(w2Ah[mt][kt], s0 + 5120 + mt * (16 * RS) + kt * 32 + laneOff);

    // ---- dynamic work stealing over row chunks ----
    for (;;) {
        u32 base;
        if (lane == 0) base = atomicAdd(&g_row_ctr, (u32)CHUNK);
        base = __shfl_sync(0xFFFFFFFFu, base, 0);
        if (base >= (u32)rows) break;
        int mend = (int)base + CHUNK;
        if (mend > rows) mend = rows;

        for (int m = (int)base; m < mend; m++) {
            const float* xb = x + (size_t)m * 1024;
            float acc[32];
#pragma unroll
            for (int i = 0; i < 32; i++) acc[i] = 0.f;

            // ---- stage 1, kt-blocked (X liveness halved) ----
#pragma unroll
            for (int kt = 0; kt < 2; kt++) {
                float4 u0, u1, u2, u3;
                {
                    int base2 = lq * 32 + 16 * kt + 4 * lr;
                    u0 = *(const float4*)(xb + base2);          // mt=0 rows lq
                    u1 = *(const float4*)(xb + base2 + 256);    // mt=0 rows lq+8
                    u2 = *(const float4*)(xb + base2 + 512);    // mt=1
                    u3 = *(const float4*)(xb + base2 + 768);
                }
                u32 XAh[2][4], XAl[2][4];
                split2(u0.x, u0.y, XAh[0][0], XAl[0][0]);
                split2(u1.x, u1.y, XAh[0][1], XAl[0][1]);
                split2(u0.z, u0.w, XAh[0][2], XAl[0][2]);
                split2(u1.z, u1.w, XAh[0][3], XAl[0][3]);
                split2(u2.x, u2.y, XAh[1][0], XAl[1][0]);
                split2(u3.x, u3.y, XAh[1][1], XAl[1][1]);
                split2(u2.z, u2.w, XAh[1][2], XAl[1][2]);
                split2(u3.z, u3.w, XAh[1][3], XAl[1][3]);

                // pass A: Ah x Bh ; pass C: Al x Bh (persistent w1Bh)
#pragma unroll
                for (int mt = 0; mt < 2; mt++)
#pragma unroll
                    for (int nt = 0; nt < 4; nt++) {
                        float* c = &acc[(mt * 4 + nt) * 4];
                        mma_bf16(c, XAh[mt], w1Bh[kt][nt]);
                        mma_bf16(c, XAl[mt], w1Bh[kt][nt]);
                    }
                // pass B: Ah x Bl (w1 lo frags loaded transiently from smem)
#pragma unroll
                for (int a = 0; a < 2; a++) {
                    u32 r[4];
                    ldm_x4(r, s0 + 2560 + a * (16 * RS) + kt * 32 + laneOff);
                    u32 b0[2] = { r[0], r[2] };   // nt = 2a
                    u32 b1[2] = { r[1], r[3] };   // nt = 2a+1
#pragma unroll
                    for (int mt = 0; mt < 2; mt++) {
                        mma_bf16(&acc[(mt * 4 + 2 * a) * 4],     XAh[mt], b0);
                        mma_bf16(&acc[(mt * 4 + 2 * a + 1) * 4], XAh[mt], b1);
                    }
                }
            }

            // ---- stage 2, kt-blocked; acc halves die into TB frags ----
            float acc2[32];
#pragma unroll
            for (int t = 0; t < 8; t++) {
                float4 b4 = pbias4[t * 32 + lane];
                acc2[t*4+0] = b4.x; acc2[t*4+1] = b4.y;
                acc2[t*4+2] = b4.z; acc2[t*4+3] = b4.w;
            }
#pragma unroll
            for (int kt = 0; kt < 2; kt++) {
                u32 TBh[4][2], TBl[4][2];
#pragma unroll
                for (int nt = 0; nt < 4; nt++) {
                    float* c = &acc[(kt * 4 + nt) * 4];
                    u32 h01, l01, h23, l23;
                    split2(c[0], c[1], h01, l01);
                    split2(c[2], c[3], h23, l23);
                    TBh[nt][0] = movm(h01);
                    TBh[nt][1] = movm(h23);
                    TBl[nt][0] = movm(l01);
                    TBl[nt][1] = movm(l23);
                }
#pragma unroll
                for (int mt = 0; mt < 2; mt++)
#pragma unroll
                    for (int nt = 0; nt < 4; nt++) {
                        float* c = &acc2[(mt * 4 + nt) * 4];
                        mma_bf16(c, w2Ah[mt][kt], TBh[nt]);
                        mma_bf16(c, w2Ah[mt][kt], TBl[nt]);
                    }
#pragma unroll
                for (int mt = 0; mt < 2; mt++) {
                    u32 al[4];
                    ldm_x4(al, s0 + 7680 + mt * (16 * RS) + kt * 32 + laneOff);
#pragma unroll
                    for (int nt = 0; nt < 4; nt++)
                        mma_bf16(&acc2[(mt * 4 + nt) * 4], al, TBh[nt]);
                }
            }

            // ---- store: tau gives each lane 32B contiguous -> STG.128 ----
            float* ob = out + (size_t)m * 1024;
#pragma unroll
            for (int mt = 0; mt < 2; mt++)
#pragma unroll
                for (int h = 0; h < 2; h++) {
                    int base2 = (16 * mt + 8 * h + lq) * 32 + 8 * lr;
                    *(float4*)(ob + base2) =
                        make_float4(acc2[(mt*4+0)*4+2*h], acc2[(mt*4+0)*4+2*h+1],
                                    acc2[(mt*4+1)*4+2*h], acc2[(mt*4+1)*4+2*h+1]);
                    *(float4*)(ob + base2 + 4) =
                        make_float4(acc2[(mt*4+2)*4+2*h], acc2[(mt*4+2)*4+2*h+1],
                                    acc2[(mt*4+3)*4+2*h], acc2[(mt*4+3)*4+2*h+1]);
                }
        }
    }
}

extern "C" void kernel_launch(void* const* d_in, const int* in_sizes, int n_in,
                              void* d_out, int out_size) {
    const float* x    = (const float*)d_in[0];
    const float* w1   = (const float*)d_in[1];
    const float* w2   = (const float*)d_in[2];
    const float* bias = (const float*)d_in[3];
    float* out        = (float*)d_out;

    int rows = in_sizes[0] / 1024;    // 65536

    reset_ctr_kernel<<<1, 1>>>();     // reset steal counter (graph-safe)

    int grid = 740;                   // 5 CTAs/SM, one resident wave
    int maxg = (rows + NW - 1) / NW;
    if (grid > maxg) grid = maxg;
    kron_mma12_kernel<<<grid, NW * 32>>>(x, w1, w2, bias, out, rows);
}